// round 5
// baseline (speedup 1.0000x reference)
#include <cuda_runtime.h>
#include <cuda_bf16.h>
#include <math.h>
#include <stdint.h>

#define HID 128
#define NPIX (4*256*256)
#define NL 4
#define NTILES 2048
#define NUNITS (NTILES*2)
#define GRID_LAYER 304

// ---------------------------------------------------------------------------
// Device globals
// ---------------------------------------------------------------------------
__device__ float g_buf0[(size_t)NPIX * HID];
__device__ float g_buf1[(size_t)NPIX * HID];
__device__ unsigned short g_whi[NL * 4 * 8192];
__device__ unsigned short g_wlo[NL * 4 * 8192];
__device__ float g_sx[256];

// ---------------------------------------------------------------------------
// Helpers
// ---------------------------------------------------------------------------
__device__ __forceinline__ uint32_t smem_u32(const void* p) {
    uint32_t a;
    asm("{ .reg .u64 t; cvta.to.shared.u64 t, %1; cvt.u32.u64 %0, t; }" : "=r"(a) : "l"(p));
    return a;
}
__device__ __forceinline__ void ldsm4(uint32_t& r0, uint32_t& r1, uint32_t& r2, uint32_t& r3, uint32_t addr) {
    asm volatile("ldmatrix.sync.aligned.m8n8.x4.shared.b16 {%0,%1,%2,%3}, [%4];"
        : "=r"(r0), "=r"(r1), "=r"(r2), "=r"(r3) : "r"(addr));
}
__device__ __forceinline__ void mma16816(float* d, const uint32_t* a, uint32_t b0, uint32_t b1) {
    asm volatile("mma.sync.aligned.m16n8k16.row.col.f32.bf16.bf16.f32 "
        "{%0,%1,%2,%3}, {%4,%5,%6,%7}, {%8,%9}, {%0,%1,%2,%3};"
        : "+f"(d[0]), "+f"(d[1]), "+f"(d[2]), "+f"(d[3])
        : "r"(a[0]), "r"(a[1]), "r"(a[2]), "r"(a[3]), "r"(b0), "r"(b1));
}
__device__ __forceinline__ float gelu_exact(float v) {
    return 0.5f * v * (1.0f + erff(v * 0.70710678118654752f));
}
__device__ __forceinline__ uint32_t pack_hi2(float a, float b) {
    return __byte_perm(__float_as_uint(a), __float_as_uint(b), 0x7632);
}
__device__ __forceinline__ uint32_t pack_lo2(float a, float b) {
    float ra = a - __uint_as_float(__float_as_uint(a) & 0xffff0000u);
    float rb = b - __uint_as_float(__float_as_uint(b) & 0xffff0000u);
    __nv_bfloat162 p = __floats2bfloat162_rn(ra, rb);
    return *reinterpret_cast<uint32_t*>(&p);
}
__device__ __forceinline__ void decode_tile(int t, int& b, int& y, int& x0) {
    b = t >> 9;
    int r = t & 511;
    int j = r >> 1;
    x0 = (r & 1) << 7;
    if (j == 0) y = 0;
    else if (j == 1) y = 128;
    else { int tt = j >> 1; y = (j & 1) ? (256 - tt) : tt; }
}

// ---------------------------------------------------------------------------
// SMEM layout (offsets from 128B-aligned base) — per-CTA ~99KB, 2 CTAs/SM
// ---------------------------------------------------------------------------
#define SM_BHI   0u             // 4 chunks x 8KB (n-half 64 x 64k bf16)
#define SM_BLO   32768u
#define SM_A     65536u         // hi 16KB + lo 16KB (128m x 64k)
#define SM_BIAS  98304u         // cb[128], br[128], bi[128]
#define SM_RED   99840u         // 256 floats
#define SM_LOW   100864u        // low[128], lob
#define SM_DYN   (100864 + 544 + 128)

// ---------------------------------------------------------------------------
// Weight prep (combined weights -> bf16 hi/lo, swizzled smem image)
// ---------------------------------------------------------------------------
__global__ void prep_w_kernel(const float* __restrict__ wr,
                              const float* __restrict__ wi,
                              const float* __restrict__ cw,
                              unsigned short* __restrict__ whi,
                              unsigned short* __restrict__ wlo)
{
    int idx = blockIdx.x * blockDim.x + threadIdx.x;   // < 131072
    int l = idx >> 15;
    int rem = idx & 32767;
    int kc = rem >> 13;
    int rem2 = rem & 8191;
    int o = rem2 >> 6;
    int kl = rem2 & 63;
    int kg = kc * 64 + kl;
    const float* wrl = wr + (size_t)l * 16384;
    const float* wil = wi + (size_t)l * 16384;
    float v;
    if (kg < 128)
        v = cw[(size_t)l * 16384 + o * 128 + kg] + 0.5f * (wrl[kg * 128 + o] + wil[kg * 128 + o]);
    else {
        int i = kg - 128;
        v = 0.5f * (wrl[i * 128 + o] - wil[i * 128 + o]);
    }
    uint32_t u = __float_as_uint(v);
    float hf = __uint_as_float(u & 0xffff0000u);
    float lo = v - hf;
    uint32_t off = (uint32_t)o * 128 + kl * 2;
    off ^= (off >> 3) & 0x70;
    size_t cbase = (size_t)(l * 4 + kc) * 8192;
    whi[cbase + (off >> 1)] = (unsigned short)(u >> 16);
    __nv_bfloat16 lb = __float2bfloat16_rn(lo);
    wlo[cbase + (off >> 1)] = __bfloat16_as_ushort(lb);
}

// Closed-form Dirichlet: s(x) = -(1/128) * sum_{k=1}^{127} sin(pi*k*x/128)
__global__ void prep_sx_kernel(float* __restrict__ sx)
{
    int x = threadIdx.x;
    double s = 0.0;
    if (x) {
        double th = M_PI * (double)x / 128.0;
        s = sin(63.5 * th) * sin(64.0 * th) / sin(0.5 * th);
    }
    sx[x] = (float)(-s / 128.0);
}

// ---------------------------------------------------------------------------
// Input transform
// ---------------------------------------------------------------------------
__global__ void in_kernel(const float* __restrict__ x,
                          const float* __restrict__ w,
                          const float* __restrict__ bias,
                          float* __restrict__ out)
{
    int gid = blockIdx.x * blockDim.x + threadIdx.x;
    int pix = gid >> 5;
    int c4 = (gid & 31) << 2;
    int b = pix >> 16;
    int yx = pix & 65535;
    const float* xb = x + (size_t)b * 196608 + yx;
    float x0 = __ldg(xb);
    float x1 = __ldg(xb + 65536);
    float x2 = __ldg(xb + 131072);
    float4 w0 = __ldg((const float4*)(w + c4));
    float4 w1 = __ldg((const float4*)(w + 128 + c4));
    float4 w2 = __ldg((const float4*)(w + 256 + c4));
    float4 bb = __ldg((const float4*)(bias + c4));
    float4 o;
    o.x = gelu_exact(x0 * w0.x + x1 * w1.x + x2 * w2.x + bb.x);
    o.y = gelu_exact(x0 * w0.y + x1 * w1.y + x2 * w2.y + bb.y);
    o.z = gelu_exact(x0 * w0.z + x1 * w1.z + x2 * w2.z + bb.z);
    o.w = gelu_exact(x0 * w0.w + x1 * w1.w + x2 * w2.w + bb.w);
    *(float4*)(out + (size_t)pix * HID + c4) = o;
}

// Final gelu over the two fused partials
__global__ void out_finish(const float* __restrict__ part,
                           const float* __restrict__ lob,
                           float* __restrict__ out)
{
    int p = blockIdx.x * blockDim.x + threadIdx.x;
    out[p] = gelu_exact(part[p] + part[NPIX + p] + __ldg(lob));
}

// ---------------------------------------------------------------------------
// Layer kernel: 2 CTAs/SM, each owns an n-half; homogeneous warps
// ---------------------------------------------------------------------------
__global__ void __launch_bounds__(256, 2) layer_kernel(
    const float* __restrict__ hin, float* __restrict__ hout,
    const uint4* __restrict__ whiL, const uint4* __restrict__ wloL,
    const float* __restrict__ cbp, const float* __restrict__ brp,
    const float* __restrict__ bip,
    const float* __restrict__ lowp, const float* __restrict__ lobp,
    int fuse)
{
    extern __shared__ char dsm_raw[];
    uint32_t raw = smem_u32(dsm_raw);
    uint32_t sbase = (raw + 127) & ~127u;
    char* sm = dsm_raw + (sbase - raw);

    int tid = threadIdx.x;
    int wid = tid >> 5;
    int lane = tid & 31;
    int nh = blockIdx.x & 1;     // which n-half this CTA owns

    // ---- preload this n-half of B (64KB) + biases ----
    {
        uint4* bh = (uint4*)(sm + SM_BHI);
        uint4* bl = (uint4*)(sm + SM_BLO);
        #pragma unroll
        for (int q = 0; q < 8; q++) {
            int i = tid + q * 256;
            int kc = i >> 9, j = i & 511;
            bh[i] = __ldg(whiL + kc * 1024 + nh * 512 + j);
            bl[i] = __ldg(wloL + kc * 1024 + nh * 512 + j);
        }
        float* bs = (float*)(sm + SM_BIAS);
        if (tid < 128) {
            bs[tid]       = __ldg(cbp + nh * 64 + (tid & 63) + ((tid >> 6) ? 0 : 0));
        }
        // simpler: load full 128 of each bias (cheap)
        if (tid < 128) {
            bs[tid]       = __ldg(cbp + tid);
            bs[128 + tid] = __ldg(brp + tid);
            bs[256 + tid] = __ldg(bip + tid);
        }
        if (fuse) {
            float* lw = (float*)(sm + SM_LOW);
            if (tid < 128) lw[tid] = __ldg(lowp + tid);
            if (tid == 0)  lw[128] = __ldg(lobp);
        }
    }
    __syncthreads();

    // ---- per-lane ldmatrix address components ----
    int grp = lane >> 3, lr = lane & 7;
    int wm = wid & 3;        // m group (4): 32 rows each
    int wn = wid >> 2;       // n group (2): 32 cols each within the half
    uint32_t xm = (uint32_t)(lr << 4);
    uint32_t a_rowadd = (uint32_t)(lr + ((grp & 1) << 3));
    uint32_t a_c16 = (uint32_t)((grp >> 1) << 4);
    uint32_t b_rowadd = (uint32_t)(lr + ((grp >> 1) << 3));
    uint32_t b_c16 = (uint32_t)((grp & 1) << 4);
    uint32_t arow[2], brow[2];
    #pragma unroll
    for (int mt = 0; mt < 2; mt++) arow[mt] = (uint32_t)(wm * 32 + mt * 16 + a_rowadd) * 128u;
    #pragma unroll
    for (int np = 0; np < 2; np++) brow[np] = (uint32_t)(wn * 32 + np * 16 + b_rowadd) * 128u;

    // ---- conversion mapping: m = tid>>1, khalf = tid&1 (32 of 64 k) ----
    int m = tid >> 1;
    int khalf = tid & 1;
    uint32_t swz = (uint32_t)(m & 7) << 4;
    uint32_t stoff[4];
    #pragma unroll
    for (int q = 0; q < 4; q++)
        stoff[q] = (uint32_t)m * 128u + (((uint32_t)(khalf * 64 + q * 16)) ^ swz);

    const float* cbS = (const float*)(sm + SM_BIAS);
    const float* brS = cbS + 128;
    const float* biS = cbS + 256;
    const float* lowS = (const float*)(sm + SM_LOW);
    float* red = (float*)(sm + SM_RED);

    int nloc = (NUNITS - blockIdx.x + GRID_LAYER - 1) / GRID_LAYER;

    // src pointer for (unit, chunk)
    auto src_for = [&](int u, int kc) -> const float* {
        int t = u >> 1;
        int b, y, x0;
        decode_tile(t, b, y, x0);
        if (kc < 2) {
            size_t base = ((size_t)(b * 256 + y)) * 256 + x0;
            return hin + (base + m) * 128 + kc * 64 + khalf * 32;
        } else {
            int yf = (256 - y) & 255;
            size_t fbase = ((size_t)(b * 256 + yf)) * 256;
            int xf = (256 - (x0 + m)) & 255;
            return hin + (fbase + xf) * 128 + (kc - 2) * 64 + khalf * 32;
        }
    };

    float4 v[8];
    {
        const float* sp = src_for(blockIdx.x, 0);
        #pragma unroll
        for (int q = 0; q < 8; q++) v[q] = __ldg((const float4*)sp + q);
    }

    for (int i = 0; i < nloc; i++) {
        int u = blockIdx.x + i * GRID_LAYER;
        int t = u >> 1;
        int b, y, x0;
        decode_tile(t, b, y, x0);
        size_t base = ((size_t)(b * 256 + y)) * 256 + x0;

        float acc[2][4][4];
        #pragma unroll
        for (int mt = 0; mt < 2; mt++)
            #pragma unroll
            for (int nt = 0; nt < 4; nt++)
                #pragma unroll
                for (int q = 0; q < 4; q++) acc[mt][nt][q] = 0.0f;

        #pragma unroll
        for (int kc = 0; kc < 4; kc++) {
            // pack current chunk (in v) to bf16 hi/lo
            uint4 H[4], L[4];
            #pragma unroll
            for (int q = 0; q < 4; q++) {
                float4 f0 = v[2 * q], f1 = v[2 * q + 1];
                H[q].x = pack_hi2(f0.x, f0.y); L[q].x = pack_lo2(f0.x, f0.y);
                H[q].y = pack_hi2(f0.z, f0.w); L[q].y = pack_lo2(f0.z, f0.w);
                H[q].z = pack_hi2(f1.x, f1.y); L[q].z = pack_lo2(f1.x, f1.y);
                H[q].w = pack_hi2(f1.z, f1.w); L[q].w = pack_lo2(f1.z, f1.w);
            }
            __syncthreads();    // A buffer free (all warps done with prev chunk)
            {
                char* hi = sm + SM_A;
                char* lo = hi + 16384;
                #pragma unroll
                for (int q = 0; q < 4; q++) {
                    *(uint4*)(hi + stoff[q]) = H[q];
                    *(uint4*)(lo + stoff[q]) = L[q];
                }
            }
            __syncthreads();    // A visible

            // prefetch next chunk's source (overlaps MMA)
            bool have_next = (kc < 3) || (i + 1 < nloc);
            if (have_next) {
                const float* sp = (kc < 3) ? src_for(u, kc + 1)
                                           : src_for(u + GRID_LAYER, 0);
                #pragma unroll
                for (int q = 0; q < 8; q++) v[q] = __ldg((const float4*)sp + q);
            }

            // ---- MMA over chunk kc ----
            uint32_t aHi = sbase + SM_A;
            uint32_t aLo = aHi + 16384u;
            uint32_t bHi = sbase + SM_BHI + (uint32_t)kc * 8192u;
            uint32_t bLo = bHi + 32768u;
            #pragma unroll
            for (int ks = 0; ks < 4; ks++) {
                uint32_t acb = ((uint32_t)(ks * 32) + a_c16) ^ xm;
                uint32_t bcb = ((uint32_t)(ks * 32) + b_c16) ^ xm;
                uint32_t ah[2][4], al[2][4];
                #pragma unroll
                for (int mt = 0; mt < 2; mt++) {
                    ldsm4(ah[mt][0], ah[mt][1], ah[mt][2], ah[mt][3], aHi + arow[mt] + acb);
                    ldsm4(al[mt][0], al[mt][1], al[mt][2], al[mt][3], aLo + arow[mt] + acb);
                }
                #pragma unroll
                for (int np = 0; np < 2; np++) {
                    uint32_t bh[4], bl[4];
                    ldsm4(bh[0], bh[1], bh[2], bh[3], bHi + brow[np] + bcb);
                    ldsm4(bl[0], bl[1], bl[2], bl[3], bLo + brow[np] + bcb);
                    #pragma unroll
                    for (int mt = 0; mt < 2; mt++) {
                        mma16816(acc[mt][np * 2],     ah[mt], bh[0], bh[1]);
                        mma16816(acc[mt][np * 2 + 1], ah[mt], bh[2], bh[3]);
                        mma16816(acc[mt][np * 2],     ah[mt], bl[0], bl[1]);
                        mma16816(acc[mt][np * 2 + 1], ah[mt], bl[2], bl[3]);
                        mma16816(acc[mt][np * 2],     al[mt], bh[0], bh[1]);
                        mma16816(acc[mt][np * 2 + 1], al[mt], bh[2], bh[3]);
                    }
                }
            }
        }

        // ---- epilogue ----
        bool row0 = (y == 0);
        if (!fuse) {
            #pragma unroll
            for (int mt = 0; mt < 2; mt++) {
                #pragma unroll
                for (int rh = 0; rh < 2; rh++) {
                    int mm = wm * 32 + mt * 16 + (lane >> 2) + rh * 8;
                    int xx = x0 + mm;
                    float sxv = row0 ? g_sx[xx] : 0.0f;
                    float* orow = hout + (base + mm) * 128;
                    #pragma unroll
                    for (int nt = 0; nt < 4; nt++) {
                        int n = nh * 64 + wn * 32 + nt * 8 + (lane & 3) * 2;
                        float v0 = acc[mt][nt][rh * 2]     + cbS[n];
                        float v1 = acc[mt][nt][rh * 2 + 1] + cbS[n + 1];
                        if (row0) {
                            v0 += biS[n] * sxv;
                            v1 += biS[n + 1] * sxv;
                            if (xx == 0) { v0 += brS[n]; v1 += brS[n + 1]; }
                        }
                        float2 o;
                        o.x = gelu_exact(v0);
                        o.y = gelu_exact(v1);
                        *(float2*)(orow + n) = o;
                    }
                }
            }
        } else {
            // fused final layer: per-half partial of sum_n gelu(v_n)*low[n]
            float part[2][2];
            #pragma unroll
            for (int mt = 0; mt < 2; mt++) {
                #pragma unroll
                for (int rh = 0; rh < 2; rh++) {
                    int mm = wm * 32 + mt * 16 + (lane >> 2) + rh * 8;
                    int xx = x0 + mm;
                    float sxv = row0 ? g_sx[xx] : 0.0f;
                    float p = 0.0f;
                    #pragma unroll
                    for (int nt = 0; nt < 4; nt++) {
                        int n = nh * 64 + wn * 32 + nt * 8 + (lane & 3) * 2;
                        float v0 = acc[mt][nt][rh * 2]     + cbS[n];
                        float v1 = acc[mt][nt][rh * 2 + 1] + cbS[n + 1];
                        if (row0) {
                            v0 += biS[n] * sxv;
                            v1 += biS[n + 1] * sxv;
                            if (xx == 0) { v0 += brS[n]; v1 += brS[n + 1]; }
                        }
                        p += gelu_exact(v0) * lowS[n] + gelu_exact(v1) * lowS[n + 1];
                    }
                    p += __shfl_xor_sync(0xffffffffu, p, 1);
                    p += __shfl_xor_sync(0xffffffffu, p, 2);
                    part[mt][rh] = p;
                }
            }
            if ((lane & 3) == 0) {
                #pragma unroll
                for (int mt = 0; mt < 2; mt++)
                    #pragma unroll
                    for (int rh = 0; rh < 2; rh++) {
                        int mm = wm * 32 + mt * 16 + (lane >> 2) + rh * 8;
                        red[wn * 128 + mm] = part[mt][rh];
                    }
            }
            __syncthreads();
            if (tid < 128)
                hout[(size_t)nh * NPIX + base + tid] = red[tid] + red[128 + tid];
            __syncthreads();
        }
    }
}

// ---------------------------------------------------------------------------
extern "C" void kernel_launch(void* const* d_in, const int* in_sizes, int n_in,
                              void* d_out, int out_size)
{
    const float* x   = (const float*)d_in[0];
    const float* liw = (const float*)d_in[1];
    const float* lib = (const float*)d_in[2];
    const float* wr  = (const float*)d_in[3];
    const float* wi  = (const float*)d_in[4];
    const float* br  = (const float*)d_in[5];
    const float* bi  = (const float*)d_in[6];
    const float* cw  = (const float*)d_in[7];
    const float* cb  = (const float*)d_in[8];
    const float* low = (const float*)d_in[9];
    const float* lob = (const float*)d_in[10];
    float* out = (float*)d_out;

    float *buf0, *buf1, *sx;
    unsigned short *whi, *wlo;
    cudaGetSymbolAddress((void**)&buf0, g_buf0);
    cudaGetSymbolAddress((void**)&buf1, g_buf1);
    cudaGetSymbolAddress((void**)&whi, g_whi);
    cudaGetSymbolAddress((void**)&wlo, g_wlo);
    cudaGetSymbolAddress((void**)&sx, g_sx);

    cudaFuncSetAttribute(layer_kernel, cudaFuncAttributeMaxDynamicSharedMemorySize, SM_DYN);

    prep_w_kernel<<<512, 256>>>(wr, wi, cw, whi, wlo);
    prep_sx_kernel<<<1, 256>>>(sx);
    in_kernel<<<NPIX * 32 / 256, 256>>>(x, liw, lib, buf0);

    float* bufs[2] = { buf0, buf1 };
    for (int l = 0; l < NL; l++) {
        int fuse = (l == NL - 1) ? 1 : 0;
        layer_kernel<<<GRID_LAYER, 256, SM_DYN>>>(
            bufs[l & 1], bufs[(l & 1) ^ 1],
            (const uint4*)(whi + (size_t)l * 4 * 8192),
            (const uint4*)(wlo + (size_t)l * 4 * 8192),
            cb + l * HID, br + l * HID, bi + l * HID,
            low, lob, fuse);
    }
    // fused layer (l=3) wrote partials into bufs[0]
    out_finish<<<NPIX / 256, 256>>>(buf0, lob, out);
}

// round 6
// speedup vs baseline: 1.5718x; 1.5718x over previous
#include <cuda_runtime.h>
#include <cuda_bf16.h>
#include <math.h>
#include <stdint.h>

#define HID 128
#define NPIX (4*256*256)
#define NL 4
#define NTILES 2048
#define GRID 152

// ---------------------------------------------------------------------------
// Device globals: activations as bf16 hi/lo pairs (exact fp32 split)
// ---------------------------------------------------------------------------
__device__ unsigned short g_h0[(size_t)NPIX * HID];
__device__ unsigned short g_l0[(size_t)NPIX * HID];
__device__ unsigned short g_h1[(size_t)NPIX * HID];
__device__ unsigned short g_l1[(size_t)NPIX * HID];
__device__ unsigned short g_whi[NL * 4 * 8192];
__device__ unsigned short g_wlo[NL * 4 * 8192];
__device__ float g_sx[256];

// ---------------------------------------------------------------------------
// Helpers
// ---------------------------------------------------------------------------
__device__ __forceinline__ uint32_t smem_u32(const void* p) {
    uint32_t a;
    asm("{ .reg .u64 t; cvta.to.shared.u64 t, %1; cvt.u32.u64 %0, t; }" : "=r"(a) : "l"(p));
    return a;
}
__device__ __forceinline__ void ldsm4(uint32_t& r0, uint32_t& r1, uint32_t& r2, uint32_t& r3, uint32_t addr) {
    asm volatile("ldmatrix.sync.aligned.m8n8.x4.shared.b16 {%0,%1,%2,%3}, [%4];"
        : "=r"(r0), "=r"(r1), "=r"(r2), "=r"(r3) : "r"(addr));
}
__device__ __forceinline__ void mma16816(float* d, const uint32_t* a, uint32_t b0, uint32_t b1) {
    asm volatile("mma.sync.aligned.m16n8k16.row.col.f32.bf16.bf16.f32 "
        "{%0,%1,%2,%3}, {%4,%5,%6,%7}, {%8,%9}, {%0,%1,%2,%3};"
        : "+f"(d[0]), "+f"(d[1]), "+f"(d[2]), "+f"(d[3])
        : "r"(a[0]), "r"(a[1]), "r"(a[2]), "r"(a[3]), "r"(b0), "r"(b1));
}
#define CP16(dst, src) asm volatile("cp.async.cg.shared.global [%0], [%1], 16;" :: "r"(dst), "l"(src))
#define CP_COMMIT()    asm volatile("cp.async.commit_group;" ::: "memory")
#define CP_WAIT1()     asm volatile("cp.async.wait_group 1;" ::: "memory")

__device__ __forceinline__ float gelu_exact(float v) {
    return 0.5f * v * (1.0f + erff(v * 0.70710678118654752f));
}
__device__ __forceinline__ uint32_t pack_hi2(float a, float b) {
    return __byte_perm(__float_as_uint(a), __float_as_uint(b), 0x7632);
}
__device__ __forceinline__ uint32_t pack_lo2(float a, float b) {
    float ra = a - __uint_as_float(__float_as_uint(a) & 0xffff0000u);
    float rb = b - __uint_as_float(__float_as_uint(b) & 0xffff0000u);
    __nv_bfloat162 p = __floats2bfloat162_rn(ra, rb);
    return *reinterpret_cast<uint32_t*>(&p);
}
__device__ __forceinline__ void decode_tile(int t, int& b, int& y, int& x0) {
    b = t >> 9;
    int r = t & 511;
    int j = r >> 1;
    x0 = (r & 1) << 7;
    if (j == 0) y = 0;
    else if (j == 1) y = 128;
    else { int tt = j >> 1; y = (j & 1) ? (256 - tt) : tt; }
}

// ---------------------------------------------------------------------------
// SMEM layout: A 3 stages x 32KB | B hi 64KB | B lo 64KB | red 2KB
// ---------------------------------------------------------------------------
#define SM_BHI  98304u
#define SM_BLO  163840u
#define SM_RED  229376u
#define SM_DYN  231424

// ---------------------------------------------------------------------------
// Weight prep (combined weights -> bf16 hi/lo, swizzled smem image)
// ---------------------------------------------------------------------------
__global__ void prep_w_kernel(const float* __restrict__ wr,
                              const float* __restrict__ wi,
                              const float* __restrict__ cw,
                              unsigned short* __restrict__ whi,
                              unsigned short* __restrict__ wlo)
{
    int idx = blockIdx.x * blockDim.x + threadIdx.x;   // < 131072
    int l = idx >> 15;
    int rem = idx & 32767;
    int kc = rem >> 13;
    int rem2 = rem & 8191;
    int o = rem2 >> 6;
    int kl = rem2 & 63;
    int kg = kc * 64 + kl;
    const float* wrl = wr + (size_t)l * 16384;
    const float* wil = wi + (size_t)l * 16384;
    float v;
    if (kg < 128)
        v = cw[(size_t)l * 16384 + o * 128 + kg] + 0.5f * (wrl[kg * 128 + o] + wil[kg * 128 + o]);
    else {
        int i = kg - 128;
        v = 0.5f * (wrl[i * 128 + o] - wil[i * 128 + o]);
    }
    uint32_t u = __float_as_uint(v);
    float hf = __uint_as_float(u & 0xffff0000u);
    float lo = v - hf;
    uint32_t off = (uint32_t)o * 128 + kl * 2;
    off ^= (off >> 3) & 0x70;
    size_t cbase = (size_t)(l * 4 + kc) * 8192;
    whi[cbase + (off >> 1)] = (unsigned short)(u >> 16);
    __nv_bfloat16 lb = __float2bfloat16_rn(lo);
    wlo[cbase + (off >> 1)] = __bfloat16_as_ushort(lb);
}

// Closed-form Dirichlet: s(x) = -(1/128) * sum_{k=1}^{127} sin(pi*k*x/128)
__global__ void prep_sx_kernel(float* __restrict__ sx)
{
    int x = threadIdx.x;
    double s = 0.0;
    if (x) {
        double th = M_PI * (double)x / 128.0;
        s = sin(63.5 * th) * sin(64.0 * th) / sin(0.5 * th);
    }
    sx[x] = (float)(-s / 128.0);
}

// ---------------------------------------------------------------------------
// Input transform -> bf16 hi/lo buffers
// ---------------------------------------------------------------------------
__global__ void in_kernel(const float* __restrict__ x,
                          const float* __restrict__ w,
                          const float* __restrict__ bias,
                          unsigned short* __restrict__ oh,
                          unsigned short* __restrict__ ol)
{
    int gid = blockIdx.x * blockDim.x + threadIdx.x;
    int pix = gid >> 5;
    int c4 = (gid & 31) << 2;
    int b = pix >> 16;
    int yx = pix & 65535;
    const float* xb = x + (size_t)b * 196608 + yx;
    float x0 = __ldg(xb);
    float x1 = __ldg(xb + 65536);
    float x2 = __ldg(xb + 131072);
    float4 w0 = __ldg((const float4*)(w + c4));
    float4 w1 = __ldg((const float4*)(w + 128 + c4));
    float4 w2 = __ldg((const float4*)(w + 256 + c4));
    float4 bb = __ldg((const float4*)(bias + c4));
    float4 o;
    o.x = gelu_exact(x0 * w0.x + x1 * w1.x + x2 * w2.x + bb.x);
    o.y = gelu_exact(x0 * w0.y + x1 * w1.y + x2 * w2.y + bb.y);
    o.z = gelu_exact(x0 * w0.z + x1 * w1.z + x2 * w2.z + bb.z);
    o.w = gelu_exact(x0 * w0.w + x1 * w1.w + x2 * w2.w + bb.w);
    uint2 hv, lv;
    hv.x = pack_hi2(o.x, o.y); hv.y = pack_hi2(o.z, o.w);
    lv.x = pack_lo2(o.x, o.y); lv.y = pack_lo2(o.z, o.w);
    *(uint2*)((uint32_t*)oh + (size_t)pix * 64 + (c4 >> 1)) = hv;
    *(uint2*)((uint32_t*)ol + (size_t)pix * 64 + (c4 >> 1)) = lv;
}

// ---------------------------------------------------------------------------
// Layer kernel: persistent, cp.async 3-stage pipeline, 1 bar/chunk
// ---------------------------------------------------------------------------
__global__ void __launch_bounds__(512, 1) layer_kernel(
    const unsigned short* __restrict__ hH, const unsigned short* __restrict__ hL,
    unsigned short* __restrict__ oH, unsigned short* __restrict__ oL,
    const uint4* __restrict__ whiL, const uint4* __restrict__ wloL,
    const float* __restrict__ cbp, const float* __restrict__ brp,
    const float* __restrict__ bip, const float* __restrict__ lowp,
    const float* __restrict__ lobp, float* __restrict__ gout, int fuse)
{
    extern __shared__ char dsm_raw[];
    uint32_t raw = smem_u32(dsm_raw);
    uint32_t sbase = (raw + 127) & ~127u;
    char* sm = dsm_raw + (sbase - raw);

    int tid = threadIdx.x;
    int wid = tid >> 5;
    int lane = tid & 31;
    int wm = wid & 3;        // 4 m-groups x 32 rows
    int wn = wid >> 2;       // 4 n-groups x 32 cols

    // cp.async mapping: m = tid>>2 pixel row, q = tid&3 (16 k each)
    int m = tid >> 2;
    int q = tid & 3;
    uint32_t swz = (uint32_t)(m & 7) << 4;
    uint32_t off0 = (uint32_t)m * 128u + (((uint32_t)q * 32u) ^ swz);
    uint32_t off1 = (uint32_t)m * 128u + (((uint32_t)q * 32u + 16u) ^ swz);

    int nloc = (NTILES - blockIdx.x + GRID - 1) / GRID;
    int totalC = nloc * 4;

    auto issue_chunk = [&](int cc) {
        if (cc < totalC) {
            int i2 = cc >> 2, kc = cc & 3;
            int t = blockIdx.x + i2 * GRID;
            int b, y, x0;
            decode_tile(t, b, y, x0);
            size_t pix;
            if (kc < 2) {
                pix = ((size_t)(b * 256 + y)) * 256 + x0 + m;
            } else {
                int yf = (256 - y) & 255;
                int xf = (256 - (x0 + m)) & 255;
                pix = ((size_t)(b * 256 + yf)) * 256 + xf;
            }
            int kc2 = kc & 1;
            const unsigned short* sH = hH + pix * 128 + kc2 * 64 + q * 16;
            const unsigned short* sL = hL + pix * 128 + kc2 * 64 + q * 16;
            uint32_t stb = sbase + (uint32_t)(cc % 3) * 32768u;
            CP16(stb + off0, sH);
            CP16(stb + off1, sH + 8);
            CP16(stb + 16384u + off0, sL);
            CP16(stb + 16384u + off1, sL + 8);
        }
        CP_COMMIT();
    };

    // prologue: issue first two chunks, then load B while they fly
    issue_chunk(0);
    issue_chunk(1);
    {
        uint4* bh = (uint4*)(sm + SM_BHI);
        uint4* bl = (uint4*)(sm + SM_BLO);
        #pragma unroll
        for (int qq = 0; qq < 8; qq++) {
            bh[tid + qq * 512] = __ldg(whiL + tid + qq * 512);
            bl[tid + qq * 512] = __ldg(wloL + tid + qq * 512);
        }
    }
    __syncthreads();

    // ldmatrix per-lane address components
    int grp = lane >> 3, lr = lane & 7;
    uint32_t xm = (uint32_t)(lr << 4);
    uint32_t a_rowadd = (uint32_t)(lr + ((grp & 1) << 3));
    uint32_t a_c16 = (uint32_t)((grp >> 1) << 4);
    uint32_t b_rowadd = (uint32_t)(lr + ((grp >> 1) << 3));
    uint32_t b_c16 = (uint32_t)((grp & 1) << 4);
    uint32_t arow[2], brow[2];
    #pragma unroll
    for (int mt = 0; mt < 2; mt++) arow[mt] = (uint32_t)(wm * 32 + mt * 16 + a_rowadd) * 128u;
    #pragma unroll
    for (int np = 0; np < 2; np++) brow[np] = (uint32_t)(wn * 32 + np * 16 + b_rowadd) * 128u;

    // hoisted per-thread bias values (n indices fixed)
    float cbv[8];
    #pragma unroll
    for (int nt = 0; nt < 4; nt++) {
        int n = wn * 32 + nt * 8 + (lane & 3) * 2;
        cbv[nt * 2]     = __ldg(cbp + n);
        cbv[nt * 2 + 1] = __ldg(cbp + n + 1);
    }
    float* red = (float*)(sm + SM_RED);

    float acc[2][4][4];

    for (int cc = 0; cc < totalC; cc++) {
        int kc = cc & 3;
        int st = cc % 3;
        CP_WAIT1();
        __syncthreads();
        issue_chunk(cc + 2);

        if (kc == 0) {
            #pragma unroll
            for (int mt = 0; mt < 2; mt++)
                #pragma unroll
                for (int nt = 0; nt < 4; nt++)
                    #pragma unroll
                    for (int z = 0; z < 4; z++) acc[mt][nt][z] = 0.0f;
        }

        // ---- MMA over chunk kc from stage st ----
        uint32_t aHi = sbase + (uint32_t)st * 32768u;
        uint32_t aLo = aHi + 16384u;
        uint32_t bHi = sbase + SM_BHI + (uint32_t)kc * 16384u;
        uint32_t bLo = sbase + SM_BLO + (uint32_t)kc * 16384u;
        #pragma unroll
        for (int ks = 0; ks < 4; ks++) {
            uint32_t acb = ((uint32_t)(ks * 32) + a_c16) ^ xm;
            uint32_t bcb = ((uint32_t)(ks * 32) + b_c16) ^ xm;
            uint32_t ah[2][4], al[2][4];
            #pragma unroll
            for (int mt = 0; mt < 2; mt++) {
                ldsm4(ah[mt][0], ah[mt][1], ah[mt][2], ah[mt][3], aHi + arow[mt] + acb);
                ldsm4(al[mt][0], al[mt][1], al[mt][2], al[mt][3], aLo + arow[mt] + acb);
            }
            #pragma unroll
            for (int np = 0; np < 2; np++) {
                uint32_t bh[4], bl[4];
                ldsm4(bh[0], bh[1], bh[2], bh[3], bHi + brow[np] + bcb);
                ldsm4(bl[0], bl[1], bl[2], bl[3], bLo + brow[np] + bcb);
                #pragma unroll
                for (int mt = 0; mt < 2; mt++) {
                    mma16816(acc[mt][np * 2],     ah[mt], bh[0], bh[1]);
                    mma16816(acc[mt][np * 2 + 1], ah[mt], bh[2], bh[3]);
                    mma16816(acc[mt][np * 2],     ah[mt], bl[0], bl[1]);
                    mma16816(acc[mt][np * 2 + 1], ah[mt], bl[2], bl[3]);
                    mma16816(acc[mt][np * 2],     al[mt], bh[0], bh[1]);
                    mma16816(acc[mt][np * 2 + 1], al[mt], bh[2], bh[3]);
                }
            }
        }

        if (kc == 3) {
            // ---- epilogue for tile (cc>>2) ----
            int t = blockIdx.x + (cc >> 2) * GRID;
            int b, y, x0;
            decode_tile(t, b, y, x0);
            size_t base = ((size_t)(b * 256 + y)) * 256 + x0;
            bool row0 = (y == 0);

            if (!fuse) {
                #pragma unroll
                for (int mt = 0; mt < 2; mt++) {
                    #pragma unroll
                    for (int rh = 0; rh < 2; rh++) {
                        int mm = wm * 32 + mt * 16 + (lane >> 2) + rh * 8;
                        int xx = x0 + mm;
                        float sxv = row0 ? __ldg(&g_sx[xx]) : 0.0f;
                        size_t pix = base + mm;
                        uint32_t* rowH = (uint32_t*)oH + pix * 64;
                        uint32_t* rowL = (uint32_t*)oL + pix * 64;
                        #pragma unroll
                        for (int nt = 0; nt < 4; nt++) {
                            int n = wn * 32 + nt * 8 + (lane & 3) * 2;
                            float v0 = acc[mt][nt][rh * 2]     + cbv[nt * 2];
                            float v1 = acc[mt][nt][rh * 2 + 1] + cbv[nt * 2 + 1];
                            if (row0) {
                                v0 += __ldg(bip + n) * sxv;
                                v1 += __ldg(bip + n + 1) * sxv;
                                if (xx == 0) { v0 += __ldg(brp + n); v1 += __ldg(brp + n + 1); }
                            }
                            float g0 = gelu_exact(v0);
                            float g1 = gelu_exact(v1);
                            rowH[n >> 1] = pack_hi2(g0, g1);
                            rowL[n >> 1] = pack_lo2(g0, g1);
                        }
                    }
                }
            } else {
                // fused: out[pix] = gelu( sum_n gelu(v_n)*low[n] + lob )
                #pragma unroll
                for (int mt = 0; mt < 2; mt++) {
                    #pragma unroll
                    for (int rh = 0; rh < 2; rh++) {
                        int mm = wm * 32 + mt * 16 + (lane >> 2) + rh * 8;
                        int xx = x0 + mm;
                        float sxv = row0 ? __ldg(&g_sx[xx]) : 0.0f;
                        float p = 0.0f;
                        #pragma unroll
                        for (int nt = 0; nt < 4; nt++) {
                            int n = wn * 32 + nt * 8 + (lane & 3) * 2;
                            float v0 = acc[mt][nt][rh * 2]     + cbv[nt * 2];
                            float v1 = acc[mt][nt][rh * 2 + 1] + cbv[nt * 2 + 1];
                            if (row0) {
                                v0 += __ldg(bip + n) * sxv;
                                v1 += __ldg(bip + n + 1) * sxv;
                                if (xx == 0) { v0 += __ldg(brp + n); v1 += __ldg(brp + n + 1); }
                            }
                            p += gelu_exact(v0) * __ldg(lowp + n)
                               + gelu_exact(v1) * __ldg(lowp + n + 1);
                        }
                        p += __shfl_xor_sync(0xffffffffu, p, 1);
                        p += __shfl_xor_sync(0xffffffffu, p, 2);
                        if ((lane & 3) == 0) red[wn * 128 + mm] = p;
                    }
                }
                __syncthreads();
                if (tid < 128) {
                    float s = red[tid] + red[128 + tid] + red[256 + tid] + red[384 + tid];
                    gout[base + tid] = gelu_exact(s + __ldg(lobp));
                }
            }
        }
    }
}

// ---------------------------------------------------------------------------
extern "C" void kernel_launch(void* const* d_in, const int* in_sizes, int n_in,
                              void* d_out, int out_size)
{
    const float* x   = (const float*)d_in[0];
    const float* liw = (const float*)d_in[1];
    const float* lib = (const float*)d_in[2];
    const float* wr  = (const float*)d_in[3];
    const float* wi  = (const float*)d_in[4];
    const float* br  = (const float*)d_in[5];
    const float* bi  = (const float*)d_in[6];
    const float* cw  = (const float*)d_in[7];
    const float* cb  = (const float*)d_in[8];
    const float* low = (const float*)d_in[9];
    const float* lob = (const float*)d_in[10];
    float* out = (float*)d_out;

    unsigned short *h0, *l0, *h1, *l1, *whi, *wlo;
    float* sx;
    cudaGetSymbolAddress((void**)&h0, g_h0);
    cudaGetSymbolAddress((void**)&l0, g_l0);
    cudaGetSymbolAddress((void**)&h1, g_h1);
    cudaGetSymbolAddress((void**)&l1, g_l1);
    cudaGetSymbolAddress((void**)&whi, g_whi);
    cudaGetSymbolAddress((void**)&wlo, g_wlo);
    cudaGetSymbolAddress((void**)&sx, g_sx);

    cudaFuncSetAttribute(layer_kernel, cudaFuncAttributeMaxDynamicSharedMemorySize, SM_DYN);

    prep_w_kernel<<<512, 256>>>(wr, wi, cw, whi, wlo);
    prep_sx_kernel<<<1, 256>>>(sx);
    in_kernel<<<NPIX * 32 / 256, 256>>>(x, liw, lib, h0, l0);

    unsigned short* hs[2] = { h0, h1 };
    unsigned short* ls[2] = { l0, l1 };
    for (int l = 0; l < NL; l++) {
        int fuse = (l == NL - 1) ? 1 : 0;
        layer_kernel<<<GRID, 512, SM_DYN>>>(
            hs[l & 1], ls[l & 1], hs[(l & 1) ^ 1], ls[(l & 1) ^ 1],
            (const uint4*)(whi + (size_t)l * 4 * 8192),
            (const uint4*)(wlo + (size_t)l * 4 * 8192),
            cb + l * HID, br + l * HID, bi + l * HID,
            low, lob, out, fuse);
    }
}